// round 5
// baseline (speedup 1.0000x reference)
#include <cuda_runtime.h>

#define VOCAB 50257
#define EMBED 128
#define BATCH 64
#define NSENT 50
#define TC 20

// Scratch (no allocations allowed -> __device__ globals)
__device__ float g_m[BATCH * NSENT * EMBED];
__device__ float g_c[BATCH * NSENT * EMBED];
__device__ float g_u[BATCH * EMBED];
__device__ float g_ut[EMBED * BATCH];   // u transposed: [k][b]

// ---------------------------------------------------------------------------
// Kernel 1: embeddings.
//   blocks [0, B*NSENT): m[b,s,:] = sum_t W_A[tok] + W_AT[te],  c likewise with W_C/W_CT
//   blocks [B*NSENT, B*NSENT+B): u0[b,:] = sum_t W_B[question tok]
// 128 threads = one embed dim each; token rows are 512B contiguous -> fully coalesced.
// ---------------------------------------------------------------------------
__global__ void embed_kernel(const int* __restrict__ stories,
                             const int* __restrict__ questions,
                             const int* __restrict__ masks,
                             const float* __restrict__ WA,
                             const float* __restrict__ WB,
                             const float* __restrict__ WC,
                             const float* __restrict__ WAT,
                             const float* __restrict__ WCT) {
    int bid = blockIdx.x;
    int d = threadIdx.x;
    __shared__ int tok[TC];
    __shared__ int cnt_s;

    if (bid < BATCH * NSENT) {
        int s = bid % NSENT;
        if (d < TC) tok[d] = stories[bid * TC + d];
        if (d == 0) {
            int c = 0;
#pragma unroll
            for (int t = 0; t < TC; t++) c += (masks[bid * TC + t] == 0);
            cnt_s = c;
        }
        __syncthreads();
        float ma = 0.f, ca = 0.f;
#pragma unroll
        for (int t = 0; t < TC; t++) {
            int tk = tok[t];
            ma += __ldg(&WA[tk * EMBED + d]);
            ca += __ldg(&WC[tk * EMBED + d]);
        }
        int te = (cnt_s >= 1) ? (s + 1) : 0;
        g_m[bid * EMBED + d] = ma + WAT[te * EMBED + d];
        g_c[bid * EMBED + d] = ca + WCT[te * EMBED + d];
    } else {
        int b = bid - BATCH * NSENT;
        if (d < TC) tok[d] = questions[b * TC + d];
        __syncthreads();
        float ua = 0.f;
#pragma unroll
        for (int t = 0; t < TC; t++) ua += __ldg(&WB[tok[t] * EMBED + d]);
        g_u[b * EMBED + d] = ua;
    }
}

// ---------------------------------------------------------------------------
// Kernel 2: 3 attention hops. One block per batch, 128 threads (4 warps).
// m cached in smem (25.6 KB); c streamed from L2.
// Writes u TRANSPOSED ([k][b]) for the linear kernel's smem layout.
// ---------------------------------------------------------------------------
__global__ void hops_kernel() {
    int b = blockIdx.x;
    int tid = threadIdx.x;
    int w = tid >> 5, lane = tid & 31;
    __shared__ float m_s[NSENT * EMBED];
    __shared__ float u_s[EMBED];
    __shared__ float sc[NSENT];

    const float4* msrc = (const float4*)(g_m + b * NSENT * EMBED);
    float4* mdst = (float4*)m_s;
    for (int i = tid; i < NSENT * EMBED / 4; i += 128) mdst[i] = msrc[i];
    float u = g_u[b * EMBED + tid];
    u_s[tid] = u;
    __syncthreads();

    const float* cb = g_c + b * NSENT * EMBED + tid;

    for (int hop = 0; hop < 3; ++hop) {
        // scores: warp w handles sentences w, w+4, ...
        for (int s = w; s < NSENT; s += 4) {
            float p = 0.f;
#pragma unroll
            for (int j = 0; j < 4; ++j) {
                int dd = lane + 32 * j;
                p += m_s[s * EMBED + dd] * u_s[dd];
            }
#pragma unroll
            for (int off = 16; off; off >>= 1)
                p += __shfl_down_sync(0xffffffffu, p, off);
            if (lane == 0) sc[s] = p;
        }
        __syncthreads();
        // softmax over 50 sentences on warp 0
        if (w == 0) {
            float x0 = sc[lane];
            float x1 = (lane + 32 < NSENT) ? sc[lane + 32] : -1e30f;
            float mx = fmaxf(x0, x1);
#pragma unroll
            for (int off = 16; off; off >>= 1)
                mx = fmaxf(mx, __shfl_xor_sync(0xffffffffu, mx, off));
            float e0 = expf(x0 - mx);
            float e1 = (lane + 32 < NSENT) ? expf(x1 - mx) : 0.f;
            float sm = e0 + e1;
#pragma unroll
            for (int off = 16; off; off >>= 1)
                sm += __shfl_xor_sync(0xffffffffu, sm, off);
            float inv = 1.f / sm;
            sc[lane] = e0 * inv;
            if (lane + 32 < NSENT) sc[lane + 32] = e1 * inv;
        }
        __syncthreads();
        // o = c^T probs ; u += o
        float o = 0.f;
#pragma unroll
        for (int s = 0; s < NSENT; ++s) o += cb[s * EMBED] * sc[s];
        u += o;
        __syncthreads();   // everyone done reading sc/u_s before overwrite
        u_s[tid] = u;
        __syncthreads();
    }
    g_ut[tid * BATCH + b] = u;   // transposed for linear kernel
}

// ---------------------------------------------------------------------------
// Kernel 3: out[b,v] = dot(u[b,:], W_lin[v,:]) + b_lin[v]
// Packed f32x2 FMA (FFMA2, 2x scalar fma throughput; PTX-only per SASS docs).
// Each lane owns one vocab row and all 64 batches as 32 f32x2 accumulators.
// u lives in smem as [k][b] so each k gives broadcast LDS.128 of 4 batches.
// ---------------------------------------------------------------------------
__device__ __forceinline__ unsigned long long pk2(float lo, float hi) {
    unsigned long long r;
    asm("mov.b64 %0, {%1, %2};" : "=l"(r) : "f"(lo), "f"(hi));
    return r;
}
__device__ __forceinline__ void ffma2(unsigned long long& d, unsigned long long a,
                                      unsigned long long b, unsigned long long c) {
    asm("fma.rn.f32x2 %0, %1, %2, %3;" : "=l"(d) : "l"(a), "l"(b), "l"(c));
}
__device__ __forceinline__ void upk2(float& lo, float& hi, unsigned long long p) {
    asm("mov.b64 {%0, %1}, %2;" : "=f"(lo), "=f"(hi) : "l"(p));
}

__global__ void __launch_bounds__(128) linear_kernel(const float* __restrict__ W,
                                                     const float* __restrict__ bias,
                                                     float* __restrict__ out) {
    __shared__ float u_s[EMBED * BATCH];   // [k][b], pairs (2j,2j+1) are contiguous
    int tid = threadIdx.x;
    {
        float4* ud = (float4*)u_s;
        const float4* us = (const float4*)g_ut;
        for (int i = tid; i < EMBED * BATCH / 4; i += 128) ud[i] = us[i];
    }
    __syncthreads();

    int wgid = blockIdx.x * 4 + (tid >> 5);
    int lane = tid & 31;
    int v = wgid * 32 + lane;
    bool valid = v < VOCAB;
    int vr = valid ? v : 0;
    const float4* wrow = (const float4*)(W + vr * EMBED);
    float bv = valid ? bias[v] : 0.f;

    unsigned long long acc[32];
    unsigned long long binit = pk2(bv, bv);
#pragma unroll
    for (int j = 0; j < 32; j++) acc[j] = binit;

    const ulonglong2* up = (const ulonglong2*)u_s;
    for (int kq = 0; kq < EMBED / 4; ++kq) {     // not fully unrolled: keep body in I$ L0
        float4 wq = wrow[kq];
#pragma unroll
        for (int sk = 0; sk < 4; ++sk) {
            float wv = (sk == 0) ? wq.x : (sk == 1) ? wq.y : (sk == 2) ? wq.z : wq.w;
            unsigned long long w2 = pk2(wv, wv);
            int k = kq * 4 + sk;
            const ulonglong2* row = up + k * 16;   // 16 x ulonglong2 = 64 batches
#pragma unroll
            for (int j = 0; j < 16; ++j) {
                ulonglong2 pp = row[j];            // broadcast LDS.128, conflict-free
                ffma2(acc[2 * j],     pp.x, w2, acc[2 * j]);
                ffma2(acc[2 * j + 1], pp.y, w2, acc[2 * j + 1]);
            }
        }
    }

    if (valid) {
#pragma unroll
        for (int j = 0; j < 32; j++) {
            float lo, hi;
            upk2(lo, hi, acc[j]);
            out[(2 * j) * VOCAB + v] = lo;         // coalesced across lanes per batch
            out[(2 * j + 1) * VOCAB + v] = hi;
        }
    }
}

// ---------------------------------------------------------------------------
extern "C" void kernel_launch(void* const* d_in, const int* in_sizes, int n_in,
                              void* d_out, int out_size) {
    const int*   stories   = (const int*)d_in[0];
    const int*   questions = (const int*)d_in[1];
    const int*   masks     = (const int*)d_in[2];
    const float* WA        = (const float*)d_in[3];
    const float* WB        = (const float*)d_in[4];
    const float* WC        = (const float*)d_in[5];
    const float* WAT       = (const float*)d_in[6];
    const float* WCT       = (const float*)d_in[7];
    const float* Wlin      = (const float*)d_in[8];
    const float* blin      = (const float*)d_in[9];
    float* out = (float*)d_out;

    embed_kernel<<<BATCH * NSENT + BATCH, 128>>>(stories, questions, masks,
                                                 WA, WB, WC, WAT, WCT);
    hops_kernel<<<BATCH, 128>>>();
    // ceil(50257/32) = 1571 warp-tasks of 32 vocab rows; 4 warps/block -> 393 blocks
    linear_kernel<<<393, 128>>>(Wlin, blin, out);
}

// round 6
// speedup vs baseline: 1.0283x; 1.0283x over previous
#include <cuda_runtime.h>

#define VOCAB 50257
#define EMBED 128
#define BATCH 64
#define NSENT 50
#define TC 20

// Scratch (no allocations allowed -> __device__ globals)
__device__ float g_m[BATCH * NSENT * EMBED];
__device__ float g_c[BATCH * NSENT * EMBED];
__device__ float g_u[BATCH * EMBED];
__device__ float g_ut[EMBED * BATCH];   // u transposed: [k][b]

// ---------------------------------------------------------------------------
// Kernel 1 (v2): embeddings, float4-vectorized.
// One WARP per sentence (or per question). Lane owns a 16B slice of the
// 512B embedding row -> 40 LDG.128 per lane (vs 40 LDG.32 per thread before):
// 4x fewer issue slots for the same bytes, higher MLP.
//   warps [0, B*NSENT): m/c rows.  warps [B*NSENT, B*NSENT+B): u0 rows.
// ---------------------------------------------------------------------------
__global__ void __launch_bounds__(128) embed_kernel(
        const int* __restrict__ stories,
        const int* __restrict__ questions,
        const int* __restrict__ masks,
        const float4* __restrict__ WA4,
        const float4* __restrict__ WB4,
        const float4* __restrict__ WC4,
        const float4* __restrict__ WAT4,
        const float4* __restrict__ WCT4) {
    int wid = threadIdx.x >> 5, lane = threadIdx.x & 31;
    int idx = blockIdx.x * 4 + wid;
    __shared__ int tok[4][TC];

    if (idx < BATCH * NSENT) {
        // tokens + mask count, warp-local
        int mz = 1;
        if (lane < TC) {
            tok[wid][lane] = stories[idx * TC + lane];
            mz = masks[idx * TC + lane];
        }
        unsigned bal = __ballot_sync(0xffffffffu, (lane < TC) && (mz == 0));
        int cnt = __popc(bal);
        __syncwarp();

        float4 ma = make_float4(0.f, 0.f, 0.f, 0.f);
        float4 ca = make_float4(0.f, 0.f, 0.f, 0.f);
#pragma unroll
        for (int t = 0; t < TC; t++) {
            int tk = tok[wid][t];
            float4 a = __ldg(&WA4[tk * 32 + lane]);
            float4 c = __ldg(&WC4[tk * 32 + lane]);
            ma.x += a.x; ma.y += a.y; ma.z += a.z; ma.w += a.w;
            ca.x += c.x; ca.y += c.y; ca.z += c.z; ca.w += c.w;
        }
        int s = idx % NSENT;
        int te = (cnt >= 1) ? (s + 1) : 0;
        float4 at = WAT4[te * 32 + lane];
        float4 ct = WCT4[te * 32 + lane];
        ma.x += at.x; ma.y += at.y; ma.z += at.z; ma.w += at.w;
        ca.x += ct.x; ca.y += ct.y; ca.z += ct.z; ca.w += ct.w;
        ((float4*)g_m)[idx * 32 + lane] = ma;
        ((float4*)g_c)[idx * 32 + lane] = ca;
    } else if (idx < BATCH * NSENT + BATCH) {
        int b = idx - BATCH * NSENT;
        if (lane < TC) tok[wid][lane] = questions[b * TC + lane];
        __syncwarp();
        float4 ua = make_float4(0.f, 0.f, 0.f, 0.f);
#pragma unroll
        for (int t = 0; t < TC; t++) {
            float4 e = __ldg(&WB4[tok[wid][t] * 32 + lane]);
            ua.x += e.x; ua.y += e.y; ua.z += e.z; ua.w += e.w;
        }
        ((float4*)g_u)[b * 32 + lane] = ua;
    }
}

// ---------------------------------------------------------------------------
// Kernel 2: 3 attention hops (UNCHANGED from passing R4 version).
// ---------------------------------------------------------------------------
__global__ void hops_kernel() {
    int b = blockIdx.x;
    int tid = threadIdx.x;
    int w = tid >> 5, lane = tid & 31;
    __shared__ float m_s[NSENT * EMBED];
    __shared__ float u_s[EMBED];
    __shared__ float sc[NSENT];

    const float4* msrc = (const float4*)(g_m + b * NSENT * EMBED);
    float4* mdst = (float4*)m_s;
    for (int i = tid; i < NSENT * EMBED / 4; i += 128) mdst[i] = msrc[i];
    float u = g_u[b * EMBED + tid];
    u_s[tid] = u;
    __syncthreads();

    const float* cb = g_c + b * NSENT * EMBED + tid;

    for (int hop = 0; hop < 3; ++hop) {
        for (int s = w; s < NSENT; s += 4) {
            float p = 0.f;
#pragma unroll
            for (int j = 0; j < 4; ++j) {
                int dd = lane + 32 * j;
                p += m_s[s * EMBED + dd] * u_s[dd];
            }
#pragma unroll
            for (int off = 16; off; off >>= 1)
                p += __shfl_down_sync(0xffffffffu, p, off);
            if (lane == 0) sc[s] = p;
        }
        __syncthreads();
        if (w == 0) {
            float x0 = sc[lane];
            float x1 = (lane + 32 < NSENT) ? sc[lane + 32] : -1e30f;
            float mx = fmaxf(x0, x1);
#pragma unroll
            for (int off = 16; off; off >>= 1)
                mx = fmaxf(mx, __shfl_xor_sync(0xffffffffu, mx, off));
            float e0 = expf(x0 - mx);
            float e1 = (lane + 32 < NSENT) ? expf(x1 - mx) : 0.f;
            float sm = e0 + e1;
#pragma unroll
            for (int off = 16; off; off >>= 1)
                sm += __shfl_xor_sync(0xffffffffu, sm, off);
            float inv = 1.f / sm;
            sc[lane] = e0 * inv;
            if (lane + 32 < NSENT) sc[lane + 32] = e1 * inv;
        }
        __syncthreads();
        float o = 0.f;
#pragma unroll
        for (int s = 0; s < NSENT; ++s) o += cb[s * EMBED] * sc[s];
        u += o;
        __syncthreads();
        u_s[tid] = u;
        __syncthreads();
    }
    g_ut[tid * BATCH + b] = u;
}

// ---------------------------------------------------------------------------
// Kernel 3 (v2): out[b,v] = dot(u[b,:], W_lin[v,:]) + b_lin[v]
// FFMA2 (packed f32x2) with SOFTWARE-PIPELINED W loads: groups of 4 float4
// (16 k-values), double-buffered so group g+1's DRAM loads (cold, ~577cyc)
// overlap group g's ~1024-cycle fma body. This removes the W-latency
// exposure that dominated the previous version.
// ---------------------------------------------------------------------------
__device__ __forceinline__ unsigned long long pk2(float lo, float hi) {
    unsigned long long r;
    asm("mov.b64 %0, {%1, %2};" : "=l"(r) : "f"(lo), "f"(hi));
    return r;
}
__device__ __forceinline__ void ffma2(unsigned long long& d, unsigned long long a,
                                      unsigned long long b, unsigned long long c) {
    asm("fma.rn.f32x2 %0, %1, %2, %3;" : "=l"(d) : "l"(a), "l"(b), "l"(c));
}
__device__ __forceinline__ void upk2(float& lo, float& hi, unsigned long long p) {
    asm("mov.b64 {%0, %1}, %2;" : "=f"(lo), "=f"(hi) : "l"(p));
}

__global__ void __launch_bounds__(128) linear_kernel(const float* __restrict__ W,
                                                     const float* __restrict__ bias,
                                                     float* __restrict__ out) {
    __shared__ float u_s[EMBED * BATCH];   // [k][b]
    int tid = threadIdx.x;
    {
        float4* ud = (float4*)u_s;
        const float4* us = (const float4*)g_ut;
        for (int i = tid; i < EMBED * BATCH / 4; i += 128) ud[i] = us[i];
    }
    __syncthreads();

    int wgid = blockIdx.x * 4 + (tid >> 5);
    int lane = tid & 31;
    int v = wgid * 32 + lane;
    bool valid = v < VOCAB;
    int vr = valid ? v : 0;
    const float4* wrow = (const float4*)(W + vr * EMBED);
    float bv = valid ? bias[v] : 0.f;

    unsigned long long acc[32];
    unsigned long long binit = pk2(bv, bv);
#pragma unroll
    for (int j = 0; j < 32; j++) acc[j] = binit;

    const ulonglong2* up = (const ulonglong2*)u_s;

    // 8 groups of 4 float4 (16 k each), double-buffered
    float4 wq[4], wn[4];
#pragma unroll
    for (int i = 0; i < 4; ++i) wq[i] = wrow[i];

    for (int g = 0; g < 8; ++g) {
        if (g < 7) {
#pragma unroll
            for (int i = 0; i < 4; ++i) wn[i] = wrow[(g + 1) * 4 + i];  // prefetch
        }
#pragma unroll
        for (int i = 0; i < 4; ++i) {
#pragma unroll
            for (int sk = 0; sk < 4; ++sk) {
                float wv = (sk == 0) ? wq[i].x : (sk == 1) ? wq[i].y
                         : (sk == 2) ? wq[i].z : wq[i].w;
                unsigned long long w2 = pk2(wv, wv);
                int k = g * 16 + i * 4 + sk;
                const ulonglong2* row = up + k * 16;   // 64 batches as 8 x 16B
#pragma unroll
                for (int j = 0; j < 16; ++j) {
                    ulonglong2 pp = row[j];            // broadcast LDS.128
                    ffma2(acc[2 * j],     pp.x, w2, acc[2 * j]);
                    ffma2(acc[2 * j + 1], pp.y, w2, acc[2 * j + 1]);
                }
            }
        }
#pragma unroll
        for (int i = 0; i < 4; ++i) wq[i] = wn[i];
    }

    if (valid) {
#pragma unroll
        for (int j = 0; j < 32; j++) {
            float lo, hi;
            upk2(lo, hi, acc[j]);
            out[(2 * j) * VOCAB + v] = lo;
            out[(2 * j + 1) * VOCAB + v] = hi;
        }
    }
}

// ---------------------------------------------------------------------------
extern "C" void kernel_launch(void* const* d_in, const int* in_sizes, int n_in,
                              void* d_out, int out_size) {
    const int*   stories   = (const int*)d_in[0];
    const int*   questions = (const int*)d_in[1];
    const int*   masks     = (const int*)d_in[2];
    const float* WA        = (const float*)d_in[3];
    const float* WB        = (const float*)d_in[4];
    const float* WC        = (const float*)d_in[5];
    const float* WAT       = (const float*)d_in[6];
    const float* WCT       = (const float*)d_in[7];
    const float* Wlin      = (const float*)d_in[8];
    const float* blin      = (const float*)d_in[9];
    float* out = (float*)d_out;

    // 3200 sentence-warps + 64 question-warps, 4 warps/block -> 816 blocks
    embed_kernel<<<816, 128>>>(stories, questions, masks,
                               (const float4*)WA, (const float4*)WB,
                               (const float4*)WC, (const float4*)WAT,
                               (const float4*)WCT);
    hops_kernel<<<BATCH, 128>>>();
    linear_kernel<<<393, 128>>>(Wlin, blin, out);
}

// round 10
// speedup vs baseline: 1.0633x; 1.0340x over previous
#include <cuda_runtime.h>
#include <cuda_bf16.h>
#include <cstdint>

#define VOCAB 50257
#define EMBED 128
#define BATCH 64
#define NSENT 50
#define TC 20

#define TILE_M 128
#define NBLK ((VOCAB + TILE_M - 1) / TILE_M)   // 393

// padded row stride for ldmatrix conflict-free access: 272B = 17 x 16B
#define ROWB 272

// smem layout (bytes)
#define SM_AHI 0
#define SM_ALO (SM_AHI + TILE_M * ROWB)     // 34816
#define SM_UHI (SM_ALO + TILE_M * ROWB)     // 69632
#define SM_ULO (SM_UHI + BATCH * ROWB)      // 87040
#define SM_TOT (SM_ULO + BATCH * ROWB)      // 104448

// Scratch (no allocations allowed -> __device__ globals)
__device__ float g_m[BATCH * NSENT * EMBED];
__device__ float g_c[BATCH * NSENT * EMBED];
__device__ float g_u[BATCH * EMBED];
__device__ float g_u2[BATCH * EMBED];    // u after hops, [b][k] row-major

// ---------------------------------------------------------------------------
// helpers
// ---------------------------------------------------------------------------
__device__ __forceinline__ uint32_t smem_u32(const void* p) {
    uint32_t a;
    asm("{ .reg .u64 t; cvta.to.shared.u64 t, %1; cvt.u32.u64 %0, t; }"
        : "=r"(a) : "l"(p));
    return a;
}
__device__ __forceinline__ void ldsm_x4(uint32_t& r0, uint32_t& r1,
                                        uint32_t& r2, uint32_t& r3, uint32_t a) {
    asm volatile("ldmatrix.sync.aligned.m8n8.x4.shared.b16 {%0,%1,%2,%3}, [%4];"
                 : "=r"(r0), "=r"(r1), "=r"(r2), "=r"(r3) : "r"(a));
}
__device__ __forceinline__ void mma16816(float* d, const uint32_t* a,
                                         const uint32_t* b) {
    asm volatile(
        "mma.sync.aligned.m16n8k16.row.col.f32.bf16.bf16.f32 "
        "{%0,%1,%2,%3}, {%4,%5,%6,%7}, {%8,%9}, {%0,%1,%2,%3};"
        : "+f"(d[0]), "+f"(d[1]), "+f"(d[2]), "+f"(d[3])
        : "r"(a[0]), "r"(a[1]), "r"(a[2]), "r"(a[3]), "r"(b[0]), "r"(b[1]));
}
__device__ __forceinline__ uint32_t packbf(__nv_bfloat16 lo, __nv_bfloat16 hi) {
    uint32_t r = ((uint32_t)__bfloat16_as_ushort(hi) << 16)
               | (uint32_t)__bfloat16_as_ushort(lo);
    return r;
}
// split one float into bf16 hi + bf16 lo
__device__ __forceinline__ void split1(float x, __nv_bfloat16& h, __nv_bfloat16& l) {
    h = __float2bfloat16_rn(x);
    l = __float2bfloat16_rn(x - __bfloat162float(h));
}

// ---------------------------------------------------------------------------
// Kernel 1: embeddings (unchanged, warp-per-sentence float4)
// ---------------------------------------------------------------------------
__global__ void __launch_bounds__(128) embed_kernel(
        const int* __restrict__ stories,
        const int* __restrict__ questions,
        const int* __restrict__ masks,
        const float4* __restrict__ WA4,
        const float4* __restrict__ WB4,
        const float4* __restrict__ WC4,
        const float4* __restrict__ WAT4,
        const float4* __restrict__ WCT4) {
    int wid = threadIdx.x >> 5, lane = threadIdx.x & 31;
    int idx = blockIdx.x * 4 + wid;
    __shared__ int tok[4][TC];

    if (idx < BATCH * NSENT) {
        int mz = 1;
        if (lane < TC) {
            tok[wid][lane] = stories[idx * TC + lane];
            mz = masks[idx * TC + lane];
        }
        unsigned bal = __ballot_sync(0xffffffffu, (lane < TC) && (mz == 0));
        int cnt = __popc(bal);
        __syncwarp();

        float4 ma = make_float4(0.f, 0.f, 0.f, 0.f);
        float4 ca = make_float4(0.f, 0.f, 0.f, 0.f);
#pragma unroll
        for (int t = 0; t < TC; t++) {
            int tk = tok[wid][t];
            float4 a = __ldg(&WA4[tk * 32 + lane]);
            float4 c = __ldg(&WC4[tk * 32 + lane]);
            ma.x += a.x; ma.y += a.y; ma.z += a.z; ma.w += a.w;
            ca.x += c.x; ca.y += c.y; ca.z += c.z; ca.w += c.w;
        }
        int s = idx % NSENT;
        int te = (cnt >= 1) ? (s + 1) : 0;
        float4 at = WAT4[te * 32 + lane];
        float4 ct = WCT4[te * 32 + lane];
        ma.x += at.x; ma.y += at.y; ma.z += at.z; ma.w += at.w;
        ca.x += ct.x; ca.y += ct.y; ca.z += ct.z; ca.w += ct.w;
        ((float4*)g_m)[idx * 32 + lane] = ma;
        ((float4*)g_c)[idx * 32 + lane] = ca;
    } else if (idx < BATCH * NSENT + BATCH) {
        int b = idx - BATCH * NSENT;
        if (lane < TC) tok[wid][lane] = questions[b * TC + lane];
        __syncwarp();
        float4 ua = make_float4(0.f, 0.f, 0.f, 0.f);
#pragma unroll
        for (int t = 0; t < TC; t++) {
            float4 e = __ldg(&WB4[tok[wid][t] * 32 + lane]);
            ua.x += e.x; ua.y += e.y; ua.z += e.z; ua.w += e.w;
        }
        ((float4*)g_u)[b * 32 + lane] = ua;
    }
}

// ---------------------------------------------------------------------------
// Kernel 2: 3 attention hops (unchanged)
// ---------------------------------------------------------------------------
__global__ void hops_kernel() {
    int b = blockIdx.x;
    int tid = threadIdx.x;
    int w = tid >> 5, lane = tid & 31;
    __shared__ float m_s[NSENT * EMBED];
    __shared__ float u_s[EMBED];
    __shared__ float sc[NSENT];

    const float4* msrc = (const float4*)(g_m + b * NSENT * EMBED);
    float4* mdst = (float4*)m_s;
    for (int i = tid; i < NSENT * EMBED / 4; i += 128) mdst[i] = msrc[i];
    float u = g_u[b * EMBED + tid];
    u_s[tid] = u;
    __syncthreads();

    const float* cb = g_c + b * NSENT * EMBED + tid;

    for (int hop = 0; hop < 3; ++hop) {
        for (int s = w; s < NSENT; s += 4) {
            float p = 0.f;
#pragma unroll
            for (int j = 0; j < 4; ++j) {
                int dd = lane + 32 * j;
                p += m_s[s * EMBED + dd] * u_s[dd];
            }
#pragma unroll
            for (int off = 16; off; off >>= 1)
                p += __shfl_down_sync(0xffffffffu, p, off);
            if (lane == 0) sc[s] = p;
        }
        __syncthreads();
        if (w == 0) {
            float x0 = sc[lane];
            float x1 = (lane + 32 < NSENT) ? sc[lane + 32] : -1e30f;
            float mx = fmaxf(x0, x1);
#pragma unroll
            for (int off = 16; off; off >>= 1)
                mx = fmaxf(mx, __shfl_xor_sync(0xffffffffu, mx, off));
            float e0 = expf(x0 - mx);
            float e1 = (lane + 32 < NSENT) ? expf(x1 - mx) : 0.f;
            float sm = e0 + e1;
#pragma unroll
            for (int off = 16; off; off >>= 1)
                sm += __shfl_xor_sync(0xffffffffu, sm, off);
            float inv = 1.f / sm;
            sc[lane] = e0 * inv;
            if (lane + 32 < NSENT) sc[lane + 32] = e1 * inv;
        }
        __syncthreads();
        float o = 0.f;
#pragma unroll
        for (int s = 0; s < NSENT; ++s) o += cb[s * EMBED] * sc[s];
        u += o;
        __syncthreads();
        u_s[tid] = u;
        __syncthreads();
    }
    g_u2[b * EMBED + tid] = u;
}

// ---------------------------------------------------------------------------
// Kernel 3: out[b,v] = dot(u[b,:], W[v,:]) + bias[v] via mma.sync (HMMA bf16)
// 3-term error-compensated bf16 split: D = Whi*uhi + Whi*ulo + Wlo*uhi.
// Per CTA: 128 vocab x 64 batch x K=128. 4 warps; warp w = 32 vocab rows.
// A (W tile) row-major [m][k], B (u) [n][k] (= col-major KxN) -> row.col mma.
// ---------------------------------------------------------------------------
__global__ void __launch_bounds__(128) linear_mma_kernel(
        const float* __restrict__ W,
        const float* __restrict__ bias,
        float* __restrict__ out) {
    extern __shared__ char smem[];
    const uint32_t sbase = smem_u32(smem);
    int tid = threadIdx.x;
    int w = tid >> 5, lane = tid & 31;
    int v0 = blockIdx.x * TILE_M;

    // ---- stage W tile: warp w covers rows 32w..32w+31; lane = float4 col ----
    {
        char* ph0 = smem + SM_AHI + (32 * w) * ROWB + lane * 8;
        char* pl0 = smem + SM_ALO + (32 * w) * ROWB + lane * 8;
#pragma unroll 4
        for (int it = 0; it < 32; ++it) {
            int row = 32 * w + it;
            int gv = v0 + row;
            uint2 hv = make_uint2(0u, 0u), lv = make_uint2(0u, 0u);
            if (gv < VOCAB) {
                float4 x = __ldg((const float4*)(W + (size_t)gv * EMBED) + lane);
                __nv_bfloat16 h0, h1, h2, h3, l0, l1, l2, l3;
                split1(x.x, h0, l0); split1(x.y, h1, l1);
                split1(x.z, h2, l2); split1(x.w, h3, l3);
                hv = make_uint2(packbf(h0, h1), packbf(h2, h3));
                lv = make_uint2(packbf(l0, l1), packbf(l2, l3));
            }
            *(uint2*)(ph0 + it * ROWB) = hv;
            *(uint2*)(pl0 + it * ROWB) = lv;
        }
    }
    // ---- stage u: warps 0,1 cover the 64 batch rows ----
    if (w < 2) {
        char* ph0 = smem + SM_UHI + (32 * w) * ROWB + lane * 8;
        char* pl0 = smem + SM_ULO + (32 * w) * ROWB + lane * 8;
#pragma unroll 4
        for (int it = 0; it < 32; ++it) {
            int row = 32 * w + it;
            float4 x = *((const float4*)(g_u2 + row * EMBED) + lane);
            __nv_bfloat16 h0, h1, h2, h3, l0, l1, l2, l3;
            split1(x.x, h0, l0); split1(x.y, h1, l1);
            split1(x.z, h2, l2); split1(x.w, h3, l3);
            *(uint2*)(ph0 + it * ROWB) = make_uint2(packbf(h0, h1), packbf(h2, h3));
            *(uint2*)(pl0 + it * ROWB) = make_uint2(packbf(l0, l1), packbf(l2, l3));
        }
    }
    __syncthreads();

    // ---- per-lane ldmatrix source offsets ----
    // A (x4, one 16x16 tile): lanes 0-15 rows m0+0..15 @k0 ; 16-31 same rows @k0+8
    int ar = lane & 15;
    int ac = (lane >> 4) * 8;
    // B (x4, two 8x16 n-tiles): r = (lane&7) + (lane>=16 ? 8 : 0), c = k0 + ((lane>>3)&1)*8
    int br = (lane & 7) + ((lane & 16) ? 8 : 0);
    int bc = ((lane >> 3) & 1) * 8;

    // warp w owns vocab rows [32w, 32w+32): m-tiles at 32w and 32w+16
    uint32_t aoff0 = (uint32_t)((32 * w + ar) * ROWB + ac * 2);
    uint32_t aoff1 = aoff0 + 16 * ROWB;
    uint32_t boff = (uint32_t)(br * ROWB + bc * 2);

    float acc[2][8][4];
#pragma unroll
    for (int mi = 0; mi < 2; ++mi)
#pragma unroll
        for (int j = 0; j < 8; ++j)
#pragma unroll
            for (int q = 0; q < 4; ++q) acc[mi][j][q] = 0.f;

    // terms: (Whi,uhi), (Whi,ulo), (Wlo,uhi)
#pragma unroll
    for (int t = 0; t < 3; ++t) {
        uint32_t abase = sbase + ((t == 2) ? SM_ALO : SM_AHI);
        uint32_t ubase = sbase + ((t == 1) ? SM_ULO : SM_UHI);
#pragma unroll
        for (int ks = 0; ks < 8; ++ks) {
            uint32_t k2 = (uint32_t)(ks * 32);   // k0*2 bytes
            uint32_t A0[4], A1[4], B[16];
            ldsm_x4(A0[0], A0[1], A0[2], A0[3], abase + aoff0 + k2);
            ldsm_x4(A1[0], A1[1], A1[2], A1[3], abase + aoff1 + k2);
#pragma unroll
            for (int jp = 0; jp < 4; ++jp)
                ldsm_x4(B[4 * jp], B[4 * jp + 1], B[4 * jp + 2], B[4 * jp + 3],
                        ubase + boff + k2 + (uint32_t)(16 * jp) * ROWB);
#pragma unroll
            for (int j = 0; j < 8; ++j) {
                mma16816(acc[0][j], A0, &B[2 * j]);
                mma16816(acc[1][j], A1, &B[2 * j]);
            }
        }
    }

    // ---- epilogue: D[m = t/4 (+8)][n = (t%4)*2 (+1)] per mma tile ----
    {
        int mrow = lane >> 2;
        int ncol = (lane & 3) * 2;
#pragma unroll
        for (int mi = 0; mi < 2; ++mi) {
            int v = v0 + 32 * w + 16 * mi + mrow;
            int v8 = v + 8;
            float bv = (v < VOCAB) ? __ldg(&bias[v]) : 0.f;
            float bv8 = (v8 < VOCAB) ? __ldg(&bias[v8]) : 0.f;
#pragma unroll
            for (int j = 0; j < 8; ++j) {
                int b = 8 * j + ncol;
                if (v < VOCAB) {
                    out[(size_t)b * VOCAB + v] = acc[mi][j][0] + bv;
                    out[(size_t)(b + 1) * VOCAB + v] = acc[mi][j][1] + bv;
                }
                if (v8 < VOCAB) {
                    out[(size_t)b * VOCAB + v8] = acc[mi][j][2] + bv8;
                    out[(size_t)(b + 1) * VOCAB + v8] = acc[mi][j][3] + bv8;
                }
            }
        }
    }
}

// ---------------------------------------------------------------------------
extern "C" void kernel_launch(void* const* d_in, const int* in_sizes, int n_in,
                              void* d_out, int out_size) {
    const int*   stories   = (const int*)d_in[0];
    const int*   questions = (const int*)d_in[1];
    const int*   masks     = (const int*)d_in[2];
    const float* WA        = (const float*)d_in[3];
    const float* WB        = (const float*)d_in[4];
    const float* WC        = (const float*)d_in[5];
    const float* WAT       = (const float*)d_in[6];
    const float* WCT       = (const float*)d_in[7];
    const float* Wlin      = (const float*)d_in[8];
    const float* blin      = (const float*)d_in[9];
    float* out = (float*)d_out;

    cudaFuncSetAttribute(linear_mma_kernel,
                         cudaFuncAttributeMaxDynamicSharedMemorySize, SM_TOT);

    embed_kernel<<<816, 128>>>(stories, questions, masks,
                               (const float4*)WA, (const float4*)WB,
                               (const float4*)WC, (const float4*)WAT,
                               (const float4*)WCT);
    hops_kernel<<<BATCH, 128>>>();
    linear_mma_kernel<<<NBLK, 128, SM_TOT>>>(Wlin, blin, out);
}

// round 11
// speedup vs baseline: 1.2741x; 1.1982x over previous
#include <cuda_runtime.h>
#include <cuda_bf16.h>
#include <cstdint>

#define VOCAB 50257
#define EMBED 128
#define BATCH 64
#define NSENT 50
#define TC 20

#define TILE_M 128
#define NBLK ((VOCAB + TILE_M - 1) / TILE_M)   // 393

// padded row stride for ldmatrix conflict-free access: 272B = 17 x 16B
#define ROWB 272

// linear smem layout (bytes)
#define SM_AHI 0
#define SM_ALO (SM_AHI + TILE_M * ROWB)     // 34816
#define SM_UHI (SM_ALO + TILE_M * ROWB)     // 69632
#define SM_ULO (SM_UHI + BATCH * ROWB)      // 87040
#define SM_BIAS (SM_ULO + BATCH * ROWB)     // 104448
#define SM_TOT (SM_BIAS + 512)              // 104960

// fused kernel smem (floats): m[50*128] c[50*128] u[128] sc[64]
#define FS_M 0
#define FS_C (NSENT * EMBED)
#define FS_U (FS_C + NSENT * EMBED)
#define FS_SC (FS_U + EMBED)
#define FS_TOTF (FS_SC + 64)
#define FS_TOTB (FS_TOTF * 4)               // 51968 B

// u after hops, bf16 hi/lo split, ldmatrix row layout: [b][64 x uint32(k2j,k2j+1)]
__device__ uint32_t g_uhi[BATCH * 64];
__device__ uint32_t g_ulo[BATCH * 64];

// ---------------------------------------------------------------------------
// helpers
// ---------------------------------------------------------------------------
__device__ __forceinline__ uint32_t smem_u32(const void* p) {
    uint32_t a;
    asm("{ .reg .u64 t; cvta.to.shared.u64 t, %1; cvt.u32.u64 %0, t; }"
        : "=r"(a) : "l"(p));
    return a;
}
__device__ __forceinline__ void ldsm_x4(uint32_t& r0, uint32_t& r1,
                                        uint32_t& r2, uint32_t& r3, uint32_t a) {
    asm volatile("ldmatrix.sync.aligned.m8n8.x4.shared.b16 {%0,%1,%2,%3}, [%4];"
                 : "=r"(r0), "=r"(r1), "=r"(r2), "=r"(r3) : "r"(a));
}
__device__ __forceinline__ void mma16816(float* d, const uint32_t* a,
                                         const uint32_t* b) {
    asm volatile(
        "mma.sync.aligned.m16n8k16.row.col.f32.bf16.bf16.f32 "
        "{%0,%1,%2,%3}, {%4,%5,%6,%7}, {%8,%9}, {%0,%1,%2,%3};"
        : "+f"(d[0]), "+f"(d[1]), "+f"(d[2]), "+f"(d[3])
        : "r"(a[0]), "r"(a[1]), "r"(a[2]), "r"(a[3]), "r"(b[0]), "r"(b[1]));
}
__device__ __forceinline__ uint32_t packbf(__nv_bfloat16 lo, __nv_bfloat16 hi) {
    return ((uint32_t)__bfloat16_as_ushort(hi) << 16)
         | (uint32_t)__bfloat16_as_ushort(lo);
}
__device__ __forceinline__ void split1(float x, __nv_bfloat16& h, __nv_bfloat16& l) {
    h = __float2bfloat16_rn(x);
    l = __float2bfloat16_rn(x - __bfloat162float(h));
}

// ---------------------------------------------------------------------------
// Kernel 1 (FUSED): embeddings + 3 hops, one block per batch, 256 threads.
// m/c gathered straight into smem (no global round-trip). Gathers buffered
// 10 rows deep per table (20 LDG.128 in flight) to cover DRAM latency.
// Epilogue writes u as pre-split bf16 hi/lo in the linear kernel's B layout.
// ---------------------------------------------------------------------------
__global__ void __launch_bounds__(256) fused_kernel(
        const int* __restrict__ stories,
        const int* __restrict__ questions,
        const int* __restrict__ masks,
        const float4* __restrict__ WA4,
        const float4* __restrict__ WB4,
        const float4* __restrict__ WC4,
        const float4* __restrict__ WAT4,
        const float4* __restrict__ WCT4) {
    extern __shared__ float fsm[];
    float* m_s = fsm + FS_M;
    float* c_s = fsm + FS_C;
    float* u_s = fsm + FS_U;
    float* sc  = fsm + FS_SC;

    int b = blockIdx.x;
    int tid = threadIdx.x;
    int w = tid >> 5, lane = tid & 31;

    // ---- gather: warp w handles sentences w, w+8, ... ----
    for (int s = w; s < NSENT; s += 8) {
        int tk_l = 0, mz = 1;
        if (lane < TC) {
            tk_l = stories[(b * NSENT + s) * TC + lane];
            mz = masks[(b * NSENT + s) * TC + lane];
        }
        unsigned bal = __ballot_sync(0xffffffffu, (lane < TC) && (mz == 0));
        int te = bal ? (s + 1) : 0;
        float4 ma = WAT4[te * 32 + lane];
        float4 ca = WCT4[te * 32 + lane];
#pragma unroll
        for (int c0 = 0; c0 < TC; c0 += 10) {
            float4 ab[10], cb2[10];
#pragma unroll
            for (int i = 0; i < 10; ++i) {
                int tk = __shfl_sync(0xffffffffu, tk_l, c0 + i);
                ab[i]  = __ldg(&WA4[tk * 32 + lane]);
                cb2[i] = __ldg(&WC4[tk * 32 + lane]);
            }
#pragma unroll
            for (int i = 0; i < 10; ++i) {
                ma.x += ab[i].x;  ma.y += ab[i].y;  ma.z += ab[i].z;  ma.w += ab[i].w;
                ca.x += cb2[i].x; ca.y += cb2[i].y; ca.z += cb2[i].z; ca.w += cb2[i].w;
            }
        }
        ((float4*)m_s)[s * 32 + lane] = ma;
        ((float4*)c_s)[s * 32 + lane] = ca;
    }
    // ---- question embedding on warp 0 ----
    if (w == 0) {
        int tk_l = (lane < TC) ? questions[b * TC + lane] : 0;
        float4 ua = make_float4(0.f, 0.f, 0.f, 0.f);
#pragma unroll
        for (int c0 = 0; c0 < TC; c0 += 10) {
            float4 qb[10];
#pragma unroll
            for (int i = 0; i < 10; ++i) {
                int tk = __shfl_sync(0xffffffffu, tk_l, c0 + i);
                qb[i] = __ldg(&WB4[tk * 32 + lane]);
            }
#pragma unroll
            for (int i = 0; i < 10; ++i) {
                ua.x += qb[i].x; ua.y += qb[i].y; ua.z += qb[i].z; ua.w += qb[i].w;
            }
        }
        ((float4*)u_s)[lane] = ua;
    }
    __syncthreads();

    // ---- 3 hops (8 warps on scores; threads <128 on o) ----
    for (int hop = 0; hop < 3; ++hop) {
        for (int s = w; s < NSENT; s += 8) {
            float p = 0.f;
#pragma unroll
            for (int j = 0; j < 4; ++j) {
                int dd = lane + 32 * j;
                p += m_s[s * EMBED + dd] * u_s[dd];
            }
#pragma unroll
            for (int off = 16; off; off >>= 1)
                p += __shfl_down_sync(0xffffffffu, p, off);
            if (lane == 0) sc[s] = p;
        }
        __syncthreads();
        if (w == 0) {
            float x0 = sc[lane];
            float x1 = (lane + 32 < NSENT) ? sc[lane + 32] : -1e30f;
            float mx = fmaxf(x0, x1);
#pragma unroll
            for (int off = 16; off; off >>= 1)
                mx = fmaxf(mx, __shfl_xor_sync(0xffffffffu, mx, off));
            float e0 = expf(x0 - mx);
            float e1 = (lane + 32 < NSENT) ? expf(x1 - mx) : 0.f;
            float sm = e0 + e1;
#pragma unroll
            for (int off = 16; off; off >>= 1)
                sm += __shfl_xor_sync(0xffffffffu, sm, off);
            float inv = 1.f / sm;
            sc[lane] = e0 * inv;
            if (lane + 32 < NSENT) sc[lane + 32] = e1 * inv;
        }
        __syncthreads();
        if (tid < EMBED) {
            float o = 0.f;
#pragma unroll
            for (int s = 0; s < NSENT; ++s) o += c_s[s * EMBED + tid] * sc[s];
            float un = u_s[tid] + o;
            __syncthreads();
            u_s[tid] = un;
        } else {
            __syncthreads();
        }
        __syncthreads();
    }

    // ---- epilogue: write u split (bf16 hi/lo) in linear B row layout ----
    if (tid < 64) {
        float a = u_s[2 * tid], c = u_s[2 * tid + 1];
        __nv_bfloat16 ah, al, ch, cl;
        split1(a, ah, al);
        split1(c, ch, cl);
        g_uhi[b * 64 + tid] = packbf(ah, ch);
        g_ulo[b * 64 + tid] = packbf(al, cl);
    }
}

// ---------------------------------------------------------------------------
// Kernel 2: out[b,v] = dot(u[b,:], W[v,:]) + bias[v] via mma.sync (HMMA bf16)
// 3-term error-compensated bf16 split: D = Whi*uhi + Whi*ulo + Wlo*uhi.
// Staging: 8-row prefetch batches (MLP 8). Epilogue: smem transpose so each
// warp store is 32 consecutive v of one batch row (out rows are only 4B
// aligned: consecutive-v runs cut write sectors 2x -> 1.25x).
// ---------------------------------------------------------------------------
__global__ void __launch_bounds__(128) linear_mma_kernel(
        const float* __restrict__ W,
        const float* __restrict__ bias,
        float* __restrict__ out) {
    extern __shared__ char smem[];
    const uint32_t sbase = smem_u32(smem);
    int tid = threadIdx.x;
    int w = tid >> 5, lane = tid & 31;
    int v0 = blockIdx.x * TILE_M;

    // ---- bias to smem ----
    {
        int gv = v0 + tid;
        ((float*)(smem + SM_BIAS))[tid] = (gv < VOCAB) ? __ldg(&bias[gv]) : 0.f;
    }
    // ---- stage u (pre-split by fused kernel): raw copy, 2048 uint4 ----
    {
        const uint4* srcH = (const uint4*)g_uhi;
        const uint4* srcL = (const uint4*)g_ulo;
        for (int idx = tid; idx < 2048; idx += 128) {
            int which = idx >> 10;          // 0 = hi, 1 = lo
            int r = (idx & 1023) >> 4;      // batch row
            int q = idx & 15;               // 16B chunk
            uint4 val = which ? __ldg(&srcL[r * 16 + q]) : __ldg(&srcH[r * 16 + q]);
            *(uint4*)(smem + (which ? SM_ULO : SM_UHI) + r * ROWB + q * 16) = val;
        }
    }
    // ---- stage W tile: warp w rows 32w..32w+31, 8-row prefetch batches ----
    {
        char* ph0 = smem + SM_AHI + (32 * w) * ROWB + lane * 8;
        char* pl0 = smem + SM_ALO + (32 * w) * ROWB + lane * 8;
#pragma unroll
        for (int g = 0; g < 4; ++g) {
            float4 buf[8];
#pragma unroll
            for (int i = 0; i < 8; ++i) {
                int gv = v0 + 32 * w + g * 8 + i;
                buf[i] = (gv < VOCAB)
                    ? __ldg((const float4*)(W + (size_t)gv * EMBED) + lane)
                    : make_float4(0.f, 0.f, 0.f, 0.f);
            }
#pragma unroll
            for (int i = 0; i < 8; ++i) {
                int it = g * 8 + i;
                __nv_bfloat16 h0, h1, h2, h3, l0, l1, l2, l3;
                split1(buf[i].x, h0, l0); split1(buf[i].y, h1, l1);
                split1(buf[i].z, h2, l2); split1(buf[i].w, h3, l3);
                *(uint2*)(ph0 + it * ROWB) = make_uint2(packbf(h0, h1), packbf(h2, h3));
                *(uint2*)(pl0 + it * ROWB) = make_uint2(packbf(l0, l1), packbf(l2, l3));
            }
        }
    }
    __syncthreads();

    // ---- ldmatrix lane offsets ----
    int ar = lane & 15;
    int ac = (lane >> 4) * 8;
    int br = (lane & 7) + ((lane & 16) ? 8 : 0);
    int bc = ((lane >> 3) & 1) * 8;
    uint32_t aoff0 = (uint32_t)((32 * w + ar) * ROWB + ac * 2);
    uint32_t aoff1 = aoff0 + 16 * ROWB;
    uint32_t boff = (uint32_t)(br * ROWB + bc * 2);

    float acc[2][8][4];
#pragma unroll
    for (int mi = 0; mi < 2; ++mi)
#pragma unroll
        for (int j = 0; j < 8; ++j)
#pragma unroll
            for (int q = 0; q < 4; ++q) acc[mi][j][q] = 0.f;

    // terms: (Whi,uhi), (Whi,ulo), (Wlo,uhi)
#pragma unroll
    for (int t = 0; t < 3; ++t) {
        uint32_t abase = sbase + ((t == 2) ? SM_ALO : SM_AHI);
        uint32_t ubase = sbase + ((t == 1) ? SM_ULO : SM_UHI);
#pragma unroll
        for (int ks = 0; ks < 8; ++ks) {
            uint32_t k2 = (uint32_t)(ks * 32);
            uint32_t A0[4], A1[4], B[16];
            ldsm_x4(A0[0], A0[1], A0[2], A0[3], abase + aoff0 + k2);
            ldsm_x4(A1[0], A1[1], A1[2], A1[3], abase + aoff1 + k2);
#pragma unroll
            for (int jp = 0; jp < 4; ++jp)
                ldsm_x4(B[4 * jp], B[4 * jp + 1], B[4 * jp + 2], B[4 * jp + 3],
                        ubase + boff + k2 + (uint32_t)(16 * jp) * ROWB);
#pragma unroll
            for (int j = 0; j < 8; ++j) {
                mma16816(acc[0][j], A0, &B[2 * j]);
                mma16816(acc[1][j], A1, &B[2 * j]);
            }
        }
    }

    // ---- epilogue: transpose D via smem (stride 67 floats, conflict-free) ----
    __syncthreads();                      // all warps done reading A smem
    {
        float* smemT = (float*)(smem + SM_AHI);   // 128 x 67 floats = 34304B
        int mrow = lane >> 2;
        int ncol = (lane & 3) * 2;
#pragma unroll
        for (int mi = 0; mi < 2; ++mi) {
            int va = 32 * w + 16 * mi + mrow;
            int vb = va + 8;
#pragma unroll
            for (int j = 0; j < 8; ++j) {
                int b0 = 8 * j + ncol;
                smemT[va * 67 + b0]     = acc[mi][j][0];
                smemT[va * 67 + b0 + 1] = acc[mi][j][1];
                smemT[vb * 67 + b0]     = acc[mi][j][2];
                smemT[vb * 67 + b0 + 1] = acc[mi][j][3];
            }
        }
        __syncthreads();
        const float* bias_s = (const float*)(smem + SM_BIAS);
        // warp w stores batch rows w, w+4, ...; per store: 32 consecutive v
        for (int bb = w; bb < BATCH; bb += 4) {
            size_t rowbase = (size_t)bb * VOCAB;
#pragma unroll
            for (int vh = 0; vh < 4; ++vh) {
                int vl = vh * 32 + lane;
                int v = v0 + vl;
                if (v < VOCAB)
                    out[rowbase + v] = smemT[vl * 67 + bb] + bias_s[vl];
            }
        }
    }
}

// ---------------------------------------------------------------------------
extern "C" void kernel_launch(void* const* d_in, const int* in_sizes, int n_in,
                              void* d_out, int out_size) {
    const int*   stories   = (const int*)d_in[0];
    const int*   questions = (const int*)d_in[1];
    const int*   masks     = (const int*)d_in[2];
    const float* WA        = (const float*)d_in[3];
    const float* WB        = (const float*)d_in[4];
    const float* WC        = (const float*)d_in[5];
    const float* WAT       = (const float*)d_in[6];
    const float* WCT       = (const float*)d_in[7];
    const float* Wlin      = (const float*)d_in[8];
    const float* blin      = (const float*)d_in[9];
    float* out = (float*)d_out;

    cudaFuncSetAttribute(fused_kernel,
                         cudaFuncAttributeMaxDynamicSharedMemorySize, FS_TOTB);
    cudaFuncSetAttribute(linear_mma_kernel,
                         cudaFuncAttributeMaxDynamicSharedMemorySize, SM_TOT);

    fused_kernel<<<BATCH, 256, FS_TOTB>>>(stories, questions, masks,
                                          (const float4*)WA, (const float4*)WB,
                                          (const float4*)WC, (const float4*)WAT,
                                          (const float4*)WCT);
    linear_mma_kernel<<<NBLK, 128, SM_TOT>>>(Wlin, blin, out);
}

// round 12
// speedup vs baseline: 1.7013x; 1.3353x over previous
#include <cuda_runtime.h>
#include <cuda_bf16.h>
#include <cstdint>

#define VOCAB 50257
#define EMBED 128
#define BATCH 64
#define NSENT 50
#define TC 20

#define TILE_M 128
#define NBLK ((VOCAB + TILE_M - 1) / TILE_M)   // 393

// padded row stride for ldmatrix conflict-free access: 272B = 17 x 16B
#define ROWB 272

// linear smem layout (bytes)
#define SM_AHI 0
#define SM_ALO (SM_AHI + TILE_M * ROWB)     // 34816
#define SM_UHI (SM_ALO + TILE_M * ROWB)     // 69632
#define SM_ULO (SM_UHI + BATCH * ROWB)      // 87040
#define SM_BIAS (SM_ULO + BATCH * ROWB)     // 104448
#define SM_TOT (SM_BIAS + 512)              // 104960

// fused kernel smem (floats)
#define FS_M 0
#define FS_C (NSENT * EMBED)                 // 6400
#define FS_U (FS_C + NSENT * EMBED)          // 12800
#define FS_SC (FS_U + EMBED)                 // 12928
#define FS_OS (FS_SC + 64)                   // 12992 : osum[4][128]
#define FS_TOTF (FS_OS + 4 * EMBED)
#define FS_TOTB (FS_TOTF * 4)                // 54016 B

// u after hops, bf16 hi/lo split, ldmatrix row layout: [b][64 x uint32]
__device__ uint32_t g_uhi[BATCH * 64];
__device__ uint32_t g_ulo[BATCH * 64];

// ---------------------------------------------------------------------------
// helpers
// ---------------------------------------------------------------------------
__device__ __forceinline__ uint32_t smem_u32(const void* p) {
    uint32_t a;
    asm("{ .reg .u64 t; cvta.to.shared.u64 t, %1; cvt.u32.u64 %0, t; }"
        : "=r"(a) : "l"(p));
    return a;
}
__device__ __forceinline__ void ldsm_x4(uint32_t& r0, uint32_t& r1,
                                        uint32_t& r2, uint32_t& r3, uint32_t a) {
    asm volatile("ldmatrix.sync.aligned.m8n8.x4.shared.b16 {%0,%1,%2,%3}, [%4];"
                 : "=r"(r0), "=r"(r1), "=r"(r2), "=r"(r3) : "r"(a));
}
__device__ __forceinline__ void mma16816(float* d, const uint32_t* a,
                                         const uint32_t* b) {
    asm volatile(
        "mma.sync.aligned.m16n8k16.row.col.f32.bf16.bf16.f32 "
        "{%0,%1,%2,%3}, {%4,%5,%6,%7}, {%8,%9}, {%0,%1,%2,%3};"
        : "+f"(d[0]), "+f"(d[1]), "+f"(d[2]), "+f"(d[3])
        : "r"(a[0]), "r"(a[1]), "r"(a[2]), "r"(a[3]), "r"(b[0]), "r"(b[1]));
}
__device__ __forceinline__ uint32_t packbf(__nv_bfloat16 lo, __nv_bfloat16 hi) {
    return ((uint32_t)__bfloat16_as_ushort(hi) << 16)
         | (uint32_t)__bfloat16_as_ushort(lo);
}
__device__ __forceinline__ void split1(float x, __nv_bfloat16& h, __nv_bfloat16& l) {
    h = __float2bfloat16_rn(x);
    l = __float2bfloat16_rn(x - __bfloat162float(h));
}

// ---------------------------------------------------------------------------
// Kernel 1 (FUSED, 512 threads): embeddings + 3 hops, one block per batch.
// 16 warps on the gather (~3 sentences each, 20 LDG.128 in flight per lane
// batch); o-phase parallelized across all 4 warp-groups via smem partials.
// ---------------------------------------------------------------------------
__global__ void __launch_bounds__(512, 1) fused_kernel(
        const int* __restrict__ stories,
        const int* __restrict__ questions,
        const int* __restrict__ masks,
        const float4* __restrict__ WA4,
        const float4* __restrict__ WB4,
        const float4* __restrict__ WC4,
        const float4* __restrict__ WAT4,
        const float4* __restrict__ WCT4) {
    extern __shared__ float fsm[];
    float* m_s = fsm + FS_M;
    float* c_s = fsm + FS_C;
    float* u_s = fsm + FS_U;
    float* sc  = fsm + FS_SC;
    float* os  = fsm + FS_OS;

    int b = blockIdx.x;
    int tid = threadIdx.x;
    int w = tid >> 5, lane = tid & 31;

    // ---- gather: warp w handles sentences w, w+16, ... ----
    for (int s = w; s < NSENT; s += 16) {
        int tk_l = 0, mz = 1;
        if (lane < TC) {
            tk_l = stories[(b * NSENT + s) * TC + lane];
            mz = masks[(b * NSENT + s) * TC + lane];
        }
        unsigned bal = __ballot_sync(0xffffffffu, (lane < TC) && (mz == 0));
        int te = bal ? (s + 1) : 0;
        float4 ma = WAT4[te * 32 + lane];
        float4 ca = WCT4[te * 32 + lane];
#pragma unroll
        for (int c0 = 0; c0 < TC; c0 += 10) {
            float4 ab[10], cb2[10];
#pragma unroll
            for (int i = 0; i < 10; ++i) {
                int tk = __shfl_sync(0xffffffffu, tk_l, c0 + i);
                ab[i]  = __ldg(&WA4[tk * 32 + lane]);
                cb2[i] = __ldg(&WC4[tk * 32 + lane]);
            }
#pragma unroll
            for (int i = 0; i < 10; ++i) {
                ma.x += ab[i].x;  ma.y += ab[i].y;  ma.z += ab[i].z;  ma.w += ab[i].w;
                ca.x += cb2[i].x; ca.y += cb2[i].y; ca.z += cb2[i].z; ca.w += cb2[i].w;
            }
        }
        ((float4*)m_s)[s * 32 + lane] = ma;
        ((float4*)c_s)[s * 32 + lane] = ca;
    }
    // ---- question embedding on warp 15 (lightest gather load) ----
    if (w == 15) {
        int tk_l = (lane < TC) ? questions[b * TC + lane] : 0;
        float4 ua = make_float4(0.f, 0.f, 0.f, 0.f);
#pragma unroll
        for (int c0 = 0; c0 < TC; c0 += 10) {
            float4 qb[10];
#pragma unroll
            for (int i = 0; i < 10; ++i) {
                int tk = __shfl_sync(0xffffffffu, tk_l, c0 + i);
                qb[i] = __ldg(&WB4[tk * 32 + lane]);
            }
#pragma unroll
            for (int i = 0; i < 10; ++i) {
                ua.x += qb[i].x; ua.y += qb[i].y; ua.z += qb[i].z; ua.w += qb[i].w;
            }
        }
        ((float4*)u_s)[lane] = ua;
    }
    __syncthreads();

    // ---- 3 hops ----
    const int gstart[4] = {0, 13, 26, 38};
    const int gend[4]   = {13, 26, 38, 50};
    int grp = tid >> 7;          // warp-group 0..3
    int d = tid & 127;           // dim within group

    for (int hop = 0; hop < 3; ++hop) {
        // scores
        for (int s = w; s < NSENT; s += 16) {
            float p = 0.f;
#pragma unroll
            for (int j = 0; j < 4; ++j) {
                int dd = lane + 32 * j;
                p += m_s[s * EMBED + dd] * u_s[dd];
            }
#pragma unroll
            for (int off = 16; off; off >>= 1)
                p += __shfl_down_sync(0xffffffffu, p, off);
            if (lane == 0) sc[s] = p;
        }
        __syncthreads();
        // softmax on warp 0
        if (w == 0) {
            float x0 = sc[lane];
            float x1 = (lane + 32 < NSENT) ? sc[lane + 32] : -1e30f;
            float mx = fmaxf(x0, x1);
#pragma unroll
            for (int off = 16; off; off >>= 1)
                mx = fmaxf(mx, __shfl_xor_sync(0xffffffffu, mx, off));
            float e0 = expf(x0 - mx);
            float e1 = (lane + 32 < NSENT) ? expf(x1 - mx) : 0.f;
            float sm = e0 + e1;
#pragma unroll
            for (int off = 16; off; off >>= 1)
                sm += __shfl_xor_sync(0xffffffffu, sm, off);
            float inv = 1.f / sm;
            sc[lane] = e0 * inv;
            if (lane + 32 < NSENT) sc[lane + 32] = e1 * inv;
        }
        __syncthreads();
        // o partials: each warp-group sums its sentence slice
        {
            float o = 0.f;
            for (int s = gstart[grp]; s < gend[grp]; ++s)
                o += c_s[s * EMBED + d] * sc[s];
            os[grp * EMBED + d] = o;
        }
        __syncthreads();
        // reduce + u update
        if (tid < EMBED) {
            u_s[tid] += os[tid] + os[EMBED + tid]
                      + os[2 * EMBED + tid] + os[3 * EMBED + tid];
        }
        __syncthreads();
    }

    // ---- epilogue: u split (bf16 hi/lo) in linear B row layout ----
    if (tid < 64) {
        float a = u_s[2 * tid], c = u_s[2 * tid + 1];
        __nv_bfloat16 ah, al, ch, cl;
        split1(a, ah, al);
        split1(c, ch, cl);
        g_uhi[b * 64 + tid] = packbf(ah, ch);
        g_ulo[b * 64 + tid] = packbf(al, cl);
    }
}

// ---------------------------------------------------------------------------
// Kernel 2 (v3): 256 threads, 8 warps, warp = one 16-row m-tile.
// __launch_bounds__(256,2) -> <=128 regs -> 2 CTAs/SM (occ 25%): staging of
// one CTA overlaps MMA of the other. acc = 32 floats/thread.
// ---------------------------------------------------------------------------
__global__ void __launch_bounds__(256, 2) linear_mma_kernel(
        const float* __restrict__ W,
        const float* __restrict__ bias,
        float* __restrict__ out) {
    extern __shared__ char smem[];
    const uint32_t sbase = smem_u32(smem);
    int tid = threadIdx.x;
    int w = tid >> 5, lane = tid & 31;
    int v0 = blockIdx.x * TILE_M;

    // ---- bias to smem ----
    if (tid < TILE_M) {
        int gv = v0 + tid;
        ((float*)(smem + SM_BIAS))[tid] = (gv < VOCAB) ? __ldg(&bias[gv]) : 0.f;
    }
    // ---- stage u (pre-split): raw copy, 2048 uint4 ----
    {
        const uint4* srcH = (const uint4*)g_uhi;
        const uint4* srcL = (const uint4*)g_ulo;
        for (int idx = tid; idx < 2048; idx += 256) {
            int which = idx >> 10;
            int r = (idx & 1023) >> 4;
            int q = idx & 15;
            uint4 val = which ? __ldg(&srcL[r * 16 + q]) : __ldg(&srcH[r * 16 + q]);
            *(uint4*)(smem + (which ? SM_ULO : SM_UHI) + r * ROWB + q * 16) = val;
        }
    }
    // ---- stage W: warp w rows 16w..16w+15, 8-row prefetch batches ----
    {
        char* ph0 = smem + SM_AHI + (16 * w) * ROWB + lane * 8;
        char* pl0 = smem + SM_ALO + (16 * w) * ROWB + lane * 8;
#pragma unroll
        for (int g = 0; g < 2; ++g) {
            float4 buf[8];
#pragma unroll
            for (int i = 0; i < 8; ++i) {
                int gv = v0 + 16 * w + g * 8 + i;
                buf[i] = (gv < VOCAB)
                    ? __ldg((const float4*)(W + (size_t)gv * EMBED) + lane)
                    : make_float4(0.f, 0.f, 0.f, 0.f);
            }
#pragma unroll
            for (int i = 0; i < 8; ++i) {
                int it = g * 8 + i;
                __nv_bfloat16 h0, h1, h2, h3, l0, l1, l2, l3;
                split1(buf[i].x, h0, l0); split1(buf[i].y, h1, l1);
                split1(buf[i].z, h2, l2); split1(buf[i].w, h3, l3);
                *(uint2*)(ph0 + it * ROWB) = make_uint2(packbf(h0, h1), packbf(h2, h3));
                *(uint2*)(pl0 + it * ROWB) = make_uint2(packbf(l0, l1), packbf(l2, l3));
            }
        }
    }
    __syncthreads();

    // ---- ldmatrix lane offsets ----
    int ar = lane & 15;
    int ac = (lane >> 4) * 8;
    int br = (lane & 7) + ((lane & 16) ? 8 : 0);
    int bc = ((lane >> 3) & 1) * 8;
    uint32_t aoff = (uint32_t)((16 * w + ar) * ROWB + ac * 2);
    uint32_t boff = (uint32_t)(br * ROWB + bc * 2);

    float acc[8][4];
#pragma unroll
    for (int j = 0; j < 8; ++j)
#pragma unroll
        for (int q = 0; q < 4; ++q) acc[j][q] = 0.f;

    // terms: (Whi,uhi), (Whi,ulo), (Wlo,uhi)
#pragma unroll
    for (int t = 0; t < 3; ++t) {
        uint32_t abase = sbase + ((t == 2) ? SM_ALO : SM_AHI);
        uint32_t ubase = sbase + ((t == 1) ? SM_ULO : SM_UHI);
#pragma unroll
        for (int ks = 0; ks < 8; ++ks) {
            uint32_t k2 = (uint32_t)(ks * 32);
            uint32_t A[4], B[16];
            ldsm_x4(A[0], A[1], A[2], A[3], abase + aoff + k2);
#pragma unroll
            for (int jp = 0; jp < 4; ++jp)
                ldsm_x4(B[4 * jp], B[4 * jp + 1], B[4 * jp + 2], B[4 * jp + 3],
                        ubase + boff + k2 + (uint32_t)(16 * jp) * ROWB);
#pragma unroll
            for (int j = 0; j < 8; ++j)
                mma16816(acc[j], A, &B[2 * j]);
        }
    }

    // ---- epilogue: transpose D via smem (stride 67, conflict-free) ----
    __syncthreads();
    {
        float* smemT = (float*)(smem + SM_AHI);   // 128 x 67 floats
        int mrow = lane >> 2;
        int ncol = (lane & 3) * 2;
        int va = 16 * w + mrow;
        int vb = va + 8;
#pragma unroll
        for (int j = 0; j < 8; ++j) {
            int b0 = 8 * j + ncol;
            smemT[va * 67 + b0]     = acc[j][0];
            smemT[va * 67 + b0 + 1] = acc[j][1];
            smemT[vb * 67 + b0]     = acc[j][2];
            smemT[vb * 67 + b0 + 1] = acc[j][3];
        }
        __syncthreads();
        const float* bias_s = (const float*)(smem + SM_BIAS);
        // warp w stores batch rows w, w+8, ...; per store: 32 consecutive v
        for (int bb = w; bb < BATCH; bb += 8) {
            size_t rowbase = (size_t)bb * VOCAB;
#pragma unroll
            for (int vh = 0; vh < 4; ++vh) {
                int vl = vh * 32 + lane;
                int v = v0 + vl;
                if (v < VOCAB)
                    out[rowbase + v] = smemT[vl * 67 + bb] + bias_s[vl];
            }
        }
    }
}

// ---------------------------------------------------------------------------
extern "C" void kernel_launch(void* const* d_in, const int* in_sizes, int n_in,
                              void* d_out, int out_size) {
    const int*   stories   = (const int*)d_in[0];
    const int*   questions = (const int*)d_in[1];
    const int*   masks     = (const int*)d_in[2];
    const float* WA        = (const float*)d_in[3];
    const float* WB        = (const float*)d_in[4];
    const float* WC        = (const float*)d_in[5];
    const float* WAT       = (const float*)d_in[6];
    const float* WCT       = (const float*)d_in[7];
    const float* Wlin      = (const float*)d_in[8];
    const float* blin      = (const float*)d_in[9];
    float* out = (float*)d_out;

    cudaFuncSetAttribute(fused_kernel,
                         cudaFuncAttributeMaxDynamicSharedMemorySize, FS_TOTB);
    cudaFuncSetAttribute(linear_mma_kernel,
                         cudaFuncAttributeMaxDynamicSharedMemorySize, SM_TOT);

    fused_kernel<<<BATCH, 512, FS_TOTB>>>(stories, questions, masks,
                                          (const float4*)WA, (const float4*)WB,
                                          (const float4*)WC, (const float4*)WAT,
                                          (const float4*)WCT);
    linear_mma_kernel<<<NBLK, 256, SM_TOT>>>(Wlin, blin, out);
}